// round 15
// baseline (speedup 1.0000x reference)
#include <cuda_runtime.h>
#include <cuda_fp16.h>
#include <cstdint>

// ---------------- Problem constants ----------------
#define B_SZ     4
#define L_SZ     4096
#define DIM      768
#define D_STATE  16
#define D_CONV   4
#define D_INNER  1536
#define DT_RANK  48
#define E2       (2*D_INNER) // 3072
#define NTOK     (B_SZ*L_SZ) // 16384
#define XDBL_C   (DT_RANK + 2*D_STATE) // 80

// ---------------- Scratch ----------------
__device__ float g_dt  [2 * (size_t)NTOK * D_INNER];
__device__ float g_xdbl[2 * (size_t)NTOK * XDBL_C];

__device__ __align__(16) __half s_xf  [(size_t)NTOK * D_INNER];     // in_proj x-half fp16
__device__ __align__(16) __half s_zh  [(size_t)NTOK * D_INNER];     // z fp16
__device__ __align__(16) __half s_yh  [2 * (size_t)NTOK * D_INNER];
__device__ __align__(16) __half s_ysum[(size_t)NTOK * D_INNER];
__device__ __align__(16) __half s_xh  [(size_t)NTOK * DIM];
__device__ __align__(16) __half s_wi  [(size_t)E2 * DIM];
__device__ __align__(16) __half s_wo  [(size_t)DIM * D_INNER];
__device__ __align__(16) __half s_wx  [2 * (size_t)XDBL_C * D_INNER];
__device__ __align__(16) __half s_wd  [2 * (size_t)D_INNER * DT_RANK];
__device__ __align__(16) __half s_xch [2 * (size_t)NTOK * D_INNER];
__device__ __align__(16) __half s_dtrh[2 * (size_t)NTOK * DT_RANK];

// ---------------- helpers ----------------
__device__ __forceinline__ float softplusf(float x) {
    return (x > 20.f) ? x : log1pf(__expf(x));
}
__device__ __forceinline__ float siluf(float x) {
    return x / (1.f + __expf(-x));
}
__device__ __forceinline__ uint32_t smem_u32(const void* p) {
    uint32_t a;
    asm("{ .reg .u64 t; cvta.to.shared.u64 t, %1; cvt.u32.u64 %0, t; }" : "=r"(a) : "l"(p));
    return a;
}
__device__ __forceinline__ void ldsm4(uint32_t* r, uint32_t addr) {
    asm volatile("ldmatrix.sync.aligned.m8n8.x4.shared.b16 {%0,%1,%2,%3}, [%4];"
        : "=r"(r[0]), "=r"(r[1]), "=r"(r[2]), "=r"(r[3]) : "r"(addr));
}
__device__ __forceinline__ void mma_f16(float* c, const uint32_t* a, const uint32_t* b) {
    asm volatile("mma.sync.aligned.m16n8k16.row.col.f32.f16.f16.f32 "
        "{%0,%1,%2,%3}, {%4,%5,%6,%7}, {%8,%9}, {%0,%1,%2,%3};"
        : "+f"(c[0]), "+f"(c[1]), "+f"(c[2]), "+f"(c[3])
        : "r"(a[0]), "r"(a[1]), "r"(a[2]), "r"(a[3]), "r"(b[0]), "r"(b[1]));
}
__device__ __forceinline__ void cp16(uint32_t dst, const void* src, bool pred) {
    const int sz = pred ? 16 : 0;
    asm volatile("cp.async.cg.shared.global [%0], [%1], 16, %2;"
        :: "r"(dst), "l"(src), "r"(sz) : "memory");
}

// ---------------- batched fp32 -> fp16 conversion ----------------
#define NSEG 4
struct CvtSegs {
    const float* src[NSEG];
    __half* dst[NSEG];
    int n4[NSEG];
    int nseg;
};

__global__ void cvt_all(CvtSegs a, int total4)
{
    const int stride = gridDim.x * blockDim.x;
    for (int i = blockIdx.x * blockDim.x + threadIdx.x; i < total4; i += stride) {
        int off = i, s = 0;
        while (s < a.nseg - 1 && off >= a.n4[s]) { off -= a.n4[s]; s++; }
        float4 v = ((const float4*)a.src[s])[off];
        __half2 p{__float2half_rn(v.x), __float2half_rn(v.y)};
        __half2 q{__float2half_rn(v.z), __float2half_rn(v.w)};
        ((uint2*)a.dst[s])[off] = make_uint2(*(uint32_t*)&p, *(uint32_t*)&q);
    }
}

// ---------------- ysum ----------------
__global__ void ysum_kernel(int n_u2)
{
    const uint2* a = (const uint2*)s_yh;
    const uint2* b = (const uint2*)(s_yh + (size_t)NTOK * D_INNER);
    uint2* o = (uint2*)s_ysum;
    const int stride = gridDim.x * blockDim.x;
    for (int i = blockIdx.x * blockDim.x + threadIdx.x; i < n_u2; i += stride) {
        uint2 va = a[i];
        uint2 vb = b[i];
        __half2 r0 = __hadd2(*(__half2*)&va.x, *(__half2*)&vb.x);
        __half2 r1 = __hadd2(*(__half2*)&va.y, *(__half2*)&vb.y);
        o[i] = make_uint2(*(uint32_t*)&r0, *(uint32_t*)&r1);
    }
}

// ---------------- single-pass fp16 HMMA GEMM, rolling pointers ----------------
// epi: 0 plain fp32; 1 bias+softplus fp32; 2 fp32 + dt_r fp16 copy; 3 split both halves fp16
#define BM 128
#define BKC 32
#define PAD 40
#define NSTAGE 5

struct GArg {
    const __half *Ah, *Bh;
    const float* bias;
    float* C;
    __half *Dh;    // epi2: dt_r; epi3: z-half
    __half *Dh2;   // epi3: x-half
};

template<int BNT>
__global__ __launch_bounds__(512, 1) void gemm_sp(
    GArg g0, GArg g1, int lda, int ldb, int ldc, int M, int N, int K, int epi)
{
    constexpr int NF    = BNT / 32;
    constexpr int OFF_B = 10240;
    constexpr int STAGE = 10240 + BNT * 80;
    extern __shared__ char smem[];
    const uint32_t sbase = smem_u32(smem);
    const GArg g = (blockIdx.z == 0) ? g0 : g1;

    const int tid  = threadIdx.x;
    const int lane = tid & 31;
    const int wid  = tid >> 5;
    const int warpM = wid & 3;
    const int warpN = wid >> 2;

    int bmb, bnb;
    {
        const int nbn = gridDim.x;
        const int bid = blockIdx.y * nbn + blockIdx.x;
        const int per = 8 * nbn;
        const int grp = bid / per;
        const int r   = bid % per;
        bmb = grp * 8 + (r % 8);
        bnb = r / 8;
    }
    const int bm = bmb * BM;
    const int bn = bnb * BNT;

    float acc[2][NF][4];
    #pragma unroll
    for (int f = 0; f < 2; f++)
        #pragma unroll
        for (int gg = 0; gg < NF; gg++)
            #pragma unroll
            for (int i = 0; i < 4; i++) acc[f][gg][i] = 0.f;

    const int aRow = warpM * 32 + (lane & 15);
    const int aCol = (lane >> 4) * 8;
    const int bRow = warpN * (BNT / 4) + (lane & 7) + ((lane >> 4) & 1) * 8;
    const int bCol = ((lane >> 3) & 1) * 8;
    const uint32_t offA = (uint32_t)(aRow * PAD + aCol) * 2;
    const uint32_t offB = (uint32_t)(bRow * PAD + bCol) * 2 + OFF_B;

    const int nch = (K + BKC - 1) / BKC;

    const int rA = tid >> 2, cA = tid & 3;
    const __half* aPtr  = g.Ah + (size_t)(bm + rA) * lda + cA * 8;
    const __half* bPtr0 = g.Bh + (size_t)(bn + rA) * ldb + cA * 8;
    const __half* bPtr1 = (BNT == 256) ? (g.Bh + (size_t)(bn + rA + 128) * ldb + cA * 8) : nullptr;
    const bool vB0 = (bn + rA) < N;
    const bool vB1 = (BNT == 256) && ((bn + rA + 128) < N);
    int kkA = cA * 8;
    uint32_t stI = sbase;
    const uint32_t soA = (uint32_t)(rA * 80 + cA * 16);

    auto issue = [&](int c) {
        if (c < nch) {
            const bool vK = kkA < K;
            cp16(stI + soA, aPtr, vK);
            cp16(stI + OFF_B + soA, bPtr0, vK && vB0);
            if (BNT == 256)
                cp16(stI + OFF_B + 128 * 80 + soA, bPtr1, vK && vB1);
            aPtr += BKC; bPtr0 += BKC;
            if (BNT == 256) bPtr1 += BKC;
            kkA += BKC;
            stI += STAGE;
            if (stI == sbase + NSTAGE * STAGE) stI = sbase;
        }
        asm volatile("cp.async.commit_group;" ::: "memory");
    };

    issue(0); issue(1); issue(2); issue(3);

    uint32_t stC = sbase;
    for (int c = 0; c < nch; c++) {
        asm volatile("cp.async.wait_group 3;" ::: "memory");
        __syncthreads();
        issue(c + 4);

        #pragma unroll
        for (int ks = 0; ks < 2; ks++) {
            const uint32_t kco = ks * 32;
            uint32_t bfr[NF][2], afr[2][4];
            #pragma unroll
            for (int p = 0; p < NF / 2; p++) {
                uint32_t r4[4];
                ldsm4(r4, stC + offB + p * (16 * PAD * 2) + kco);
                bfr[2*p][0] = r4[0]; bfr[2*p][1] = r4[1];
                bfr[2*p+1][0] = r4[2]; bfr[2*p+1][1] = r4[3];
            }
            #pragma unroll
            for (int f = 0; f < 2; f++)
                ldsm4(afr[f], stC + offA + f * (16 * PAD * 2) + kco);
            #pragma unroll
            for (int f = 0; f < 2; f++)
                #pragma unroll
                for (int gg = 0; gg < NF; gg++) mma_f16(acc[f][gg], afr[f], bfr[gg]);
        }
        stC += STAGE;
        if (stC == sbase + NSTAGE * STAGE) stC = sbase;
    }

    #pragma unroll
    for (int f = 0; f < 2; f++) {
        const int r0 = bm + warpM * 32 + f * 16 + (lane >> 2);
        #pragma unroll
        for (int gg = 0; gg < NF; gg++) {
            const int col = bn + warpN * (BNT / 4) + gg * 8 + 2 * (lane & 3);
            if (col < N) {
                float v0 = acc[f][gg][0], v1 = acc[f][gg][1];
                float v2 = acc[f][gg][2], v3 = acc[f][gg][3];
                if (g.bias) {
                    const float b0 = g.bias[col], b1 = g.bias[col + 1];
                    v0 += b0; v1 += b1; v2 += b0; v3 += b1;
                }
                if (epi == 1) {
                    v0 = softplusf(v0); v1 = softplusf(v1);
                    v2 = softplusf(v2); v3 = softplusf(v3);
                }
                if (epi == 3) {
                    __half* dst = (col < D_INNER) ? g.Dh2 : g.Dh;
                    const int cc = (col < D_INNER) ? col : (col - D_INNER);
                    __half2 ha{__float2half_rn(v0), __float2half_rn(v1)};
                    __half2 hb{__float2half_rn(v2), __float2half_rn(v3)};
                    *(__half2*)(dst + (size_t)r0 * D_INNER + cc)       = ha;
                    *(__half2*)(dst + (size_t)(r0 + 8) * D_INNER + cc) = hb;
                } else {
                    *(float2*)(g.C + (size_t)r0 * ldc + col)       = make_float2(v0, v1);
                    *(float2*)(g.C + (size_t)(r0 + 8) * ldc + col) = make_float2(v2, v3);
                    if (epi == 2 && col < DT_RANK) {
                        __half2 ha{__float2half_rn(v0), __float2half_rn(v1)};
                        __half2 hb{__float2half_rn(v2), __float2half_rn(v3)};
                        *(__half2*)(g.Dh + (size_t)r0 * DT_RANK + col)       = ha;
                        *(__half2*)(g.Dh + (size_t)(r0 + 8) * DT_RANK + col) = hb;
                    }
                }
            }
        }
    }
}

// ---------------- Fused bidirectional causal conv (k=4) + SiLU ----------------
#define CTOK 32
#define CCH  128
__global__ __launch_bounds__(256) void conv_silu_kernel(
    const float* __restrict__ wf, const float* __restrict__ bf,
    const float* __restrict__ wb, const float* __restrict__ bb)
{
    const int b   = blockIdx.z;
    const int l0  = blockIdx.y * CTOK;
    const int d0  = blockIdx.x * CCH;
    const int tid = threadIdx.x;

    __shared__ float sx[CTOK + 6][CCH];

    #pragma unroll
    for (int i = tid; i < (CTOK + 6) * CCH; i += 256) {
        const int r = i / CCH;
        const int c = i % CCH;
        const int m = l0 - 3 + r;
        float v = 0.f;
        if (m >= 0 && m < L_SZ)
            v = __half2float(s_xf[((size_t)b * L_SZ + m) * D_INNER + d0 + c]);
        sx[r][c] = v;
    }
    __syncthreads();

    const int c  = tid & (CCH - 1);
    const int t0 = tid >> 7;
    const int d  = d0 + c;
    const float f0 = wf[d * 4 + 0], f1 = wf[d * 4 + 1];
    const float f2 = wf[d * 4 + 2], f3 = wf[d * 4 + 3];
    const float r0 = wb[d * 4 + 0], r1 = wb[d * 4 + 1];
    const float r2 = wb[d * 4 + 2], r3 = wb[d * 4 + 3];
    const float biasF = bf[d], biasB = bb[d];

    #pragma unroll
    for (int t = t0; t < CTOK; t += 2) {
        const int l = l0 + t;
        const float af = biasF + f0 * sx[t][c] + f1 * sx[t + 1][c]
                               + f2 * sx[t + 2][c] + f3 * sx[t + 3][c];
        s_xch[((size_t)b * L_SZ + l) * D_INNER + d] = __float2half_rn(siluf(af));
        const float ab = biasB + r0 * sx[t + 6][c] + r1 * sx[t + 5][c]
                               + r2 * sx[t + 4][c] + r3 * sx[t + 3][c];
        s_xch[((size_t)NTOK + (size_t)b * L_SZ + (L_SZ - 1 - l)) * D_INNER + d] =
            __float2half_rn(siluf(ab));
    }
}

// ---------------- Selective scan (l_len-parameterized for probe) ----------------
#define ST  64
#define SCH 64

__global__ __launch_bounds__(256) void scan_kernel(
    const float* __restrict__ A_log_f, const float* __restrict__ D_f,
    const float* __restrict__ A_log_b, const float* __restrict__ D_b,
    int l_len)
{
    const int dir = blockIdx.z;
    const int b   = blockIdx.y;
    const int d0  = blockIdx.x * SCH;
    const int tid = threadIdx.x;
    const int ch  = tid >> 2;
    const int sg  = tid & 3;
    const int d   = d0 + ch;

    const size_t dirTok = (size_t)dir * NTOK;
    const __half* xch = s_xch + dirTok * D_INNER;
    const float* dtp  = g_dt   + dirTok * D_INNER;
    const float* xdbl = g_xdbl + dirTok * XDBL_C;
    __half*      yout = s_yh   + dirTok * D_INNER;
    const float* Alog = dir ? A_log_b : A_log_f;
    const float* Dv   = dir ? D_b     : D_f;

    float A[4];
    #pragma unroll
    for (int j = 0; j < 4; j++) A[j] = -__expf(Alog[d * D_STATE + sg * 4 + j]);
    const float Dd = Dv[d];

    float h[4] = {0.f, 0.f, 0.f, 0.f};

    __shared__ float s_u [ST][SCH];
    __shared__ float s_dt[ST][SCH];
    __shared__ float s_z [ST][SCH];
    __shared__ __align__(16) float s_B[ST][D_STATE];
    __shared__ __align__(16) float s_C[ST][D_STATE];

    for (int l0 = 0; l0 < l_len; l0 += ST) {
        __syncthreads();
        #pragma unroll
        for (int i = tid; i < ST * SCH; i += 256) {
            const int t = i >> 6;
            const int c = i & 63;
            const size_t gl = ((size_t)b * L_SZ + l0 + t) * D_INNER + d0 + c;
            s_u[t][c]  = __half2float(xch[gl]);
            s_dt[t][c] = dtp[gl];
            const int lsrc = dir ? (L_SZ - 1 - (l0 + t)) : (l0 + t);
            s_z[t][c]  = __half2float(s_zh[((size_t)b * L_SZ + lsrc) * D_INNER + d0 + c]);
        }
        #pragma unroll
        for (int i = tid; i < ST * 32; i += 256) {
            const int t = i >> 5;
            const int c = i & 31;
            const float v = xdbl[((size_t)b * L_SZ + l0 + t) * XDBL_C + DT_RANK + c];
            if (c < D_STATE) s_B[t][c] = v;
            else             s_C[t][c - D_STATE] = v;
        }
        __syncthreads();

        for (int t = 0; t < ST; t++) {
            const float u   = s_u[t][ch];
            const float dtv = s_dt[t][ch];
            const float dtu = dtv * u;
            const float4 Bv = *(const float4*)&s_B[t][sg * 4];
            const float4 Cv = *(const float4*)&s_C[t][sg * 4];
            float y;
            {
                const float dA0 = __expf(dtv * A[0]);
                const float dA1 = __expf(dtv * A[1]);
                const float dA2 = __expf(dtv * A[2]);
                const float dA3 = __expf(dtv * A[3]);
                h[0] = h[0] * dA0 + dtu * Bv.x;
                h[1] = h[1] * dA1 + dtu * Bv.y;
                h[2] = h[2] * dA2 + dtu * Bv.z;
                h[3] = h[3] * dA3 + dtu * Bv.w;
                y = h[0] * Cv.x + h[1] * Cv.y + h[2] * Cv.z + h[3] * Cv.w;
            }
            y += __shfl_xor_sync(0xFFFFFFFF, y, 1);
            y += __shfl_xor_sync(0xFFFFFFFF, y, 2);
            if (sg == 0) {
                y += u * Dd;
                const int l = l0 + t;
                const int lsrc = dir ? (L_SZ - 1 - l) : l;
                const float zv = s_z[t][ch];
                yout[((size_t)b * L_SZ + lsrc) * D_INNER + d] =
                    __float2half_rn(y * siluf(zv));
            }
        }
    }
}

// ---------------- Launch ----------------
extern "C" void kernel_launch(void* const* d_in, const int* in_sizes, int n_in,
                              void* d_out, int out_size)
{
    const float* x            = (const float*)d_in[0];
    const float* in_proj_w    = (const float*)d_in[1];
    const float* out_proj_w   = (const float*)d_in[2];
    const float* conv1d_w     = (const float*)d_in[3];
    const float* conv1d_bias  = (const float*)d_in[4];
    const float* x_proj_w     = (const float*)d_in[5];
    const float* dt_proj_w    = (const float*)d_in[6];
    const float* dt_proj_bias = (const float*)d_in[7];
    const float* A_log        = (const float*)d_in[8];
    const float* Dvec         = (const float*)d_in[9];
    const float* conv1d_w_b   = (const float*)d_in[10];
    const float* conv1d_bias_b= (const float*)d_in[11];
    const float* x_proj_w_b   = (const float*)d_in[12];
    const float* dt_proj_w_b  = (const float*)d_in[13];
    const float* dt_proj_bias_b=(const float*)d_in[14];
    const float* A_log_b      = (const float*)d_in[15];
    const float* D_b          = (const float*)d_in[16];
    float* out = (float*)d_out;

    float *p_dt, *p_xdbl;
    __half *p_xf,*p_zh,*p_yh,*p_ysum,*p_xh,*p_wi,*p_wo,*p_wx,*p_wd,*p_xch,*p_dtrh;
    cudaGetSymbolAddress((void**)&p_dt,   g_dt);
    cudaGetSymbolAddress((void**)&p_xdbl, g_xdbl);
    cudaGetSymbolAddress((void**)&p_xf,   s_xf);
    cudaGetSymbolAddress((void**)&p_zh,   s_zh);
    cudaGetSymbolAddress((void**)&p_yh,   s_yh);
    cudaGetSymbolAddress((void**)&p_ysum, s_ysum);
    cudaGetSymbolAddress((void**)&p_xh,   s_xh);
    cudaGetSymbolAddress((void**)&p_wi,   s_wi);
    cudaGetSymbolAddress((void**)&p_wo,   s_wo);
    cudaGetSymbolAddress((void**)&p_wx,   s_wx);
    cudaGetSymbolAddress((void**)&p_wd,   s_wd);
    cudaGetSymbolAddress((void**)&p_xch,  s_xch);
    cudaGetSymbolAddress((void**)&p_dtrh, s_dtrh);

    cudaFuncSetAttribute((const void*)gemm_sp<256>, cudaFuncAttributeMaxDynamicSharedMemorySize,
                         NSTAGE * (10240 + 256 * 80));
    cudaFuncSetAttribute((const void*)gemm_sp<128>, cudaFuncAttributeMaxDynamicSharedMemorySize,
                         NSTAGE * (10240 + 128 * 80));

    const size_t tokDI = (size_t)NTOK * D_INNER;
    const size_t tokXD = (size_t)NTOK * XDBL_C;
    const size_t wx1   = (size_t)XDBL_C * D_INNER;
    const size_t wd1   = (size_t)D_INNER * DT_RANK;
    const size_t dtr1  = (size_t)NTOK * DT_RANK;

    // 1) small weights
    {
        CvtSegs cs{};
        cs.src[0] = x_proj_w;    cs.dst[0] = p_wx;        cs.n4[0] = (int)(wx1 / 4);
        cs.src[1] = x_proj_w_b;  cs.dst[1] = p_wx + wx1;  cs.n4[1] = (int)(wx1 / 4);
        cs.src[2] = dt_proj_w;   cs.dst[2] = p_wd;        cs.n4[2] = (int)(wd1 / 4);
        cs.src[3] = dt_proj_w_b; cs.dst[3] = p_wd + wd1;  cs.n4[3] = (int)(wd1 / 4);
        cs.nseg = 4;
        cvt_all<<<512, 256>>>(cs, cs.n4[0] + cs.n4[1] + cs.n4[2] + cs.n4[3]);
    }
    // 2) big weights
    {
        CvtSegs cs{};
        cs.src[0] = in_proj_w;   cs.dst[0] = p_wi;  cs.n4[0] = E2 * DIM / 4;
        cs.src[1] = out_proj_w;  cs.dst[1] = p_wo;  cs.n4[1] = DIM * D_INNER / 4;
        cs.nseg = 2;
        cvt_all<<<2048, 256>>>(cs, cs.n4[0] + cs.n4[1]);
    }
    // 3) x
    {
        CvtSegs cs{};
        cs.src[0] = x; cs.dst[0] = p_xh; cs.n4[0] = NTOK * DIM / 4;
        cs.nseg = 1;
        cvt_all<<<2048, 256>>>(cs, cs.n4[0]);
    }

    // 4) PROBE: 1/16-depth scan on stale scratch (output overwritten by real scan)
    //    Full grid so SOL% is representative; dur*16 ~= real scan cost.
    {
        dim3 grid(D_INNER / SCH, B_SZ, 2);
        scan_kernel<<<grid, 256>>>(A_log, Dvec, A_log_b, D_b, 256);
    }

    // 5) in_proj (16384 x 3072, K=768), both halves -> fp16
    {
        GArg a{p_xh, p_wi, nullptr, nullptr, p_zh, p_xf};
        dim3 grid(E2 / 256, NTOK / BM, 1);
        gemm_sp<256><<<grid, 512, NSTAGE*(10240+256*80)>>>(a, a, DIM, DIM, D_INNER, NTOK, E2, DIM, 3);
    }

    // 6) fused bidirectional conv + silu
    {
        dim3 grid(D_INNER / CCH, L_SZ / CTOK, B_SZ);
        conv_silu_kernel<<<grid, 256>>>(conv1d_w, conv1d_bias, conv1d_w_b, conv1d_bias_b);
    }

    // 7) x_proj both dirs (16384 x 80, K=1536)
    {
        GArg a0{p_xch,         p_wx,       nullptr, p_xdbl,         p_dtrh,        nullptr};
        GArg a1{p_xch + tokDI, p_wx + wx1, nullptr, p_xdbl + tokXD, p_dtrh + dtr1, nullptr};
        dim3 grid(1, NTOK / BM, 2);
        gemm_sp<128><<<grid, 512, NSTAGE*(10240+128*80)>>>(a0, a1, D_INNER, D_INNER, XDBL_C, NTOK, XDBL_C, D_INNER, 2);
    }

    // 8) dt_proj both dirs (16384 x 1536, K=48) + softplus
    {
        GArg a0{p_dtrh,        p_wd,       dt_proj_bias,   p_dt,         nullptr, nullptr};
        GArg a1{p_dtrh + dtr1, p_wd + wd1, dt_proj_bias_b, p_dt + tokDI, nullptr, nullptr};
        dim3 grid(D_INNER / 256, NTOK / BM, 2);
        gemm_sp<256><<<grid, 512, NSTAGE*(10240+256*80)>>>(a0, a1, DT_RANK, DT_RANK, D_INNER, NTOK, D_INNER, DT_RANK, 1);
    }

    // 9) real selective scan
    {
        dim3 grid(D_INNER / SCH, B_SZ, 2);
        scan_kernel<<<grid, 256>>>(A_log, Dvec, A_log_b, D_b, L_SZ);
    }

    // 10) ysum
    ysum_kernel<<<1024, 256>>>((int)(tokDI / 4));

    // 11) out_proj (16384 x 768, K=1536)
    {
        GArg a{p_ysum, p_wo, nullptr, out, nullptr, nullptr};
        dim3 grid(DIM / 256, NTOK / BM, 1);
        gemm_sp<256><<<grid, 512, NSTAGE*(10240+256*80)>>>(a, a, D_INNER, D_INNER, DIM, NTOK, DIM, D_INNER, 0);
    }
}

// round 16
// speedup vs baseline: 1.1766x; 1.1766x over previous
#include <cuda_runtime.h>
#include <cuda_fp16.h>
#include <cstdint>

// ---------------- Problem constants ----------------
#define B_SZ     4
#define L_SZ     4096
#define DIM      768
#define D_STATE  16
#define D_CONV   4
#define D_INNER  1536
#define DT_RANK  48
#define E2       (2*D_INNER) // 3072
#define NTOK     (B_SZ*L_SZ) // 16384
#define XDBL_C   (DT_RANK + 2*D_STATE) // 80

// ---------------- Scratch ----------------
__device__ float g_dt  [2 * (size_t)NTOK * D_INNER];
__device__ float g_xdbl[2 * (size_t)NTOK * XDBL_C];

__device__ __align__(16) __half s_xf  [(size_t)NTOK * D_INNER];
__device__ __align__(16) __half s_zh  [(size_t)NTOK * D_INNER];
__device__ __align__(16) __half s_yh  [2 * (size_t)NTOK * D_INNER];
__device__ __align__(16) __half s_ysum[(size_t)NTOK * D_INNER];
__device__ __align__(16) __half s_xh  [(size_t)NTOK * DIM];
__device__ __align__(16) __half s_wi  [(size_t)E2 * DIM];
__device__ __align__(16) __half s_wo  [(size_t)DIM * D_INNER];
__device__ __align__(16) __half s_wx  [2 * (size_t)XDBL_C * D_INNER];
__device__ __align__(16) __half s_wd  [2 * (size_t)D_INNER * DT_RANK];
__device__ __align__(16) __half s_xch [2 * (size_t)NTOK * D_INNER];
__device__ __align__(16) __half s_dtrh[2 * (size_t)NTOK * DT_RANK];

// ---------------- helpers ----------------
__device__ __forceinline__ float softplusf(float x) {
    return (x > 20.f) ? x : log1pf(__expf(x));
}
__device__ __forceinline__ float siluf(float x) {
    return x / (1.f + __expf(-x));
}
__device__ __forceinline__ uint32_t smem_u32(const void* p) {
    uint32_t a;
    asm("{ .reg .u64 t; cvta.to.shared.u64 t, %1; cvt.u32.u64 %0, t; }" : "=r"(a) : "l"(p));
    return a;
}
__device__ __forceinline__ void ldsm4(uint32_t* r, uint32_t addr) {
    asm volatile("ldmatrix.sync.aligned.m8n8.x4.shared.b16 {%0,%1,%2,%3}, [%4];"
        : "=r"(r[0]), "=r"(r[1]), "=r"(r[2]), "=r"(r[3]) : "r"(addr));
}
__device__ __forceinline__ void mma_f16(float* c, const uint32_t* a, const uint32_t* b) {
    asm volatile("mma.sync.aligned.m16n8k16.row.col.f32.f16.f16.f32 "
        "{%0,%1,%2,%3}, {%4,%5,%6,%7}, {%8,%9}, {%0,%1,%2,%3};"
        : "+f"(c[0]), "+f"(c[1]), "+f"(c[2]), "+f"(c[3])
        : "r"(a[0]), "r"(a[1]), "r"(a[2]), "r"(a[3]), "r"(b[0]), "r"(b[1]));
}
__device__ __forceinline__ void cp16(uint32_t dst, const void* src, bool pred) {
    const int sz = pred ? 16 : 0;
    asm volatile("cp.async.cg.shared.global [%0], [%1], 16, %2;"
        :: "r"(dst), "l"(src), "r"(sz) : "memory");
}

// ---------------- batched fp32 -> fp16 conversion ----------------
#define NSEG 4
struct CvtSegs {
    const float* src[NSEG];
    __half* dst[NSEG];
    int n4[NSEG];
    int nseg;
};

__global__ void cvt_all(CvtSegs a, int total4)
{
    const int stride = gridDim.x * blockDim.x;
    for (int i = blockIdx.x * blockDim.x + threadIdx.x; i < total4; i += stride) {
        int off = i, s = 0;
        while (s < a.nseg - 1 && off >= a.n4[s]) { off -= a.n4[s]; s++; }
        float4 v = ((const float4*)a.src[s])[off];
        __half2 p{__float2half_rn(v.x), __float2half_rn(v.y)};
        __half2 q{__float2half_rn(v.z), __float2half_rn(v.w)};
        ((uint2*)a.dst[s])[off] = make_uint2(*(uint32_t*)&p, *(uint32_t*)&q);
    }
}

// ---------------- ysum ----------------
__global__ void ysum_kernel(int n_u2)
{
    const uint2* a = (const uint2*)s_yh;
    const uint2* b = (const uint2*)(s_yh + (size_t)NTOK * D_INNER);
    uint2* o = (uint2*)s_ysum;
    const int stride = gridDim.x * blockDim.x;
    for (int i = blockIdx.x * blockDim.x + threadIdx.x; i < n_u2; i += stride) {
        uint2 va = a[i];
        uint2 vb = b[i];
        __half2 r0 = __hadd2(*(__half2*)&va.x, *(__half2*)&vb.x);
        __half2 r1 = __hadd2(*(__half2*)&va.y, *(__half2*)&vb.y);
        o[i] = make_uint2(*(uint32_t*)&r0, *(uint32_t*)&r1);
    }
}

// ---------------- single-pass fp16 HMMA GEMM, rolling pointers ----------------
#define BM 128
#define BKC 32
#define PAD 40
#define NSTAGE 5

struct GArg {
    const __half *Ah, *Bh;
    const float* bias;
    float* C;
    __half *Dh;
    __half *Dh2;
};

template<int BNT>
__global__ __launch_bounds__(512, 1) void gemm_sp(
    GArg g0, GArg g1, int lda, int ldb, int ldc, int M, int N, int K, int epi)
{
    constexpr int NF    = BNT / 32;
    constexpr int OFF_B = 10240;
    constexpr int STAGE = 10240 + BNT * 80;
    extern __shared__ char smem[];
    const uint32_t sbase = smem_u32(smem);
    const GArg g = (blockIdx.z == 0) ? g0 : g1;

    const int tid  = threadIdx.x;
    const int lane = tid & 31;
    const int wid  = tid >> 5;
    const int warpM = wid & 3;
    const int warpN = wid >> 2;

    int bmb, bnb;
    {
        const int nbn = gridDim.x;
        const int bid = blockIdx.y * nbn + blockIdx.x;
        const int per = 8 * nbn;
        const int grp = bid / per;
        const int r   = bid % per;
        bmb = grp * 8 + (r % 8);
        bnb = r / 8;
    }
    const int bm = bmb * BM;
    const int bn = bnb * BNT;

    float acc[2][NF][4];
    #pragma unroll
    for (int f = 0; f < 2; f++)
        #pragma unroll
        for (int gg = 0; gg < NF; gg++)
            #pragma unroll
            for (int i = 0; i < 4; i++) acc[f][gg][i] = 0.f;

    const int aRow = warpM * 32 + (lane & 15);
    const int aCol = (lane >> 4) * 8;
    const int bRow = warpN * (BNT / 4) + (lane & 7) + ((lane >> 4) & 1) * 8;
    const int bCol = ((lane >> 3) & 1) * 8;
    const uint32_t offA = (uint32_t)(aRow * PAD + aCol) * 2;
    const uint32_t offB = (uint32_t)(bRow * PAD + bCol) * 2 + OFF_B;

    const int nch = (K + BKC - 1) / BKC;

    const int rA = tid >> 2, cA = tid & 3;
    const __half* aPtr  = g.Ah + (size_t)(bm + rA) * lda + cA * 8;
    const __half* bPtr0 = g.Bh + (size_t)(bn + rA) * ldb + cA * 8;
    const __half* bPtr1 = (BNT == 256) ? (g.Bh + (size_t)(bn + rA + 128) * ldb + cA * 8) : nullptr;
    const bool vB0 = (bn + rA) < N;
    const bool vB1 = (BNT == 256) && ((bn + rA + 128) < N);
    int kkA = cA * 8;
    uint32_t stI = sbase;
    const uint32_t soA = (uint32_t)(rA * 80 + cA * 16);

    auto issue = [&](int c) {
        if (c < nch) {
            const bool vK = kkA < K;
            cp16(stI + soA, aPtr, vK);
            cp16(stI + OFF_B + soA, bPtr0, vK && vB0);
            if (BNT == 256)
                cp16(stI + OFF_B + 128 * 80 + soA, bPtr1, vK && vB1);
            aPtr += BKC; bPtr0 += BKC;
            if (BNT == 256) bPtr1 += BKC;
            kkA += BKC;
            stI += STAGE;
            if (stI == sbase + NSTAGE * STAGE) stI = sbase;
        }
        asm volatile("cp.async.commit_group;" ::: "memory");
    };

    issue(0); issue(1); issue(2); issue(3);

    uint32_t stC = sbase;
    for (int c = 0; c < nch; c++) {
        asm volatile("cp.async.wait_group 3;" ::: "memory");
        __syncthreads();
        issue(c + 4);

        #pragma unroll
        for (int ks = 0; ks < 2; ks++) {
            const uint32_t kco = ks * 32;
            uint32_t bfr[NF][2], afr[2][4];
            #pragma unroll
            for (int p = 0; p < NF / 2; p++) {
                uint32_t r4[4];
                ldsm4(r4, stC + offB + p * (16 * PAD * 2) + kco);
                bfr[2*p][0] = r4[0]; bfr[2*p][1] = r4[1];
                bfr[2*p+1][0] = r4[2]; bfr[2*p+1][1] = r4[3];
            }
            #pragma unroll
            for (int f = 0; f < 2; f++)
                ldsm4(afr[f], stC + offA + f * (16 * PAD * 2) + kco);
            #pragma unroll
            for (int f = 0; f < 2; f++)
                #pragma unroll
                for (int gg = 0; gg < NF; gg++) mma_f16(acc[f][gg], afr[f], bfr[gg]);
        }
        stC += STAGE;
        if (stC == sbase + NSTAGE * STAGE) stC = sbase;
    }

    #pragma unroll
    for (int f = 0; f < 2; f++) {
        const int r0 = bm + warpM * 32 + f * 16 + (lane >> 2);
        #pragma unroll
        for (int gg = 0; gg < NF; gg++) {
            const int col = bn + warpN * (BNT / 4) + gg * 8 + 2 * (lane & 3);
            if (col < N) {
                float v0 = acc[f][gg][0], v1 = acc[f][gg][1];
                float v2 = acc[f][gg][2], v3 = acc[f][gg][3];
                if (g.bias) {
                    const float b0 = g.bias[col], b1 = g.bias[col + 1];
                    v0 += b0; v1 += b1; v2 += b0; v3 += b1;
                }
                if (epi == 1) {
                    v0 = softplusf(v0); v1 = softplusf(v1);
                    v2 = softplusf(v2); v3 = softplusf(v3);
                }
                if (epi == 3) {
                    __half* dst = (col < D_INNER) ? g.Dh2 : g.Dh;
                    const int cc = (col < D_INNER) ? col : (col - D_INNER);
                    __half2 ha{__float2half_rn(v0), __float2half_rn(v1)};
                    __half2 hb{__float2half_rn(v2), __float2half_rn(v3)};
                    *(__half2*)(dst + (size_t)r0 * D_INNER + cc)       = ha;
                    *(__half2*)(dst + (size_t)(r0 + 8) * D_INNER + cc) = hb;
                } else {
                    *(float2*)(g.C + (size_t)r0 * ldc + col)       = make_float2(v0, v1);
                    *(float2*)(g.C + (size_t)(r0 + 8) * ldc + col) = make_float2(v2, v3);
                    if (epi == 2 && col < DT_RANK) {
                        __half2 ha{__float2half_rn(v0), __float2half_rn(v1)};
                        __half2 hb{__float2half_rn(v2), __float2half_rn(v3)};
                        *(__half2*)(g.Dh + (size_t)r0 * DT_RANK + col)       = ha;
                        *(__half2*)(g.Dh + (size_t)(r0 + 8) * DT_RANK + col) = hb;
                    }
                }
            }
        }
    }
}

// ---------------- Fused bidirectional causal conv (k=4) + SiLU ----------------
#define CTOK 32
#define CCH  128
__global__ __launch_bounds__(256) void conv_silu_kernel(
    const float* __restrict__ wf, const float* __restrict__ bf,
    const float* __restrict__ wb, const float* __restrict__ bb)
{
    const int b   = blockIdx.z;
    const int l0  = blockIdx.y * CTOK;
    const int d0  = blockIdx.x * CCH;
    const int tid = threadIdx.x;

    __shared__ float sx[CTOK + 6][CCH];

    #pragma unroll
    for (int i = tid; i < (CTOK + 6) * CCH; i += 256) {
        const int r = i / CCH;
        const int c = i % CCH;
        const int m = l0 - 3 + r;
        float v = 0.f;
        if (m >= 0 && m < L_SZ)
            v = __half2float(s_xf[((size_t)b * L_SZ + m) * D_INNER + d0 + c]);
        sx[r][c] = v;
    }
    __syncthreads();

    const int c  = tid & (CCH - 1);
    const int t0 = tid >> 7;
    const int d  = d0 + c;
    const float f0 = wf[d * 4 + 0], f1 = wf[d * 4 + 1];
    const float f2 = wf[d * 4 + 2], f3 = wf[d * 4 + 3];
    const float r0 = wb[d * 4 + 0], r1 = wb[d * 4 + 1];
    const float r2 = wb[d * 4 + 2], r3 = wb[d * 4 + 3];
    const float biasF = bf[d], biasB = bb[d];

    #pragma unroll
    for (int t = t0; t < CTOK; t += 2) {
        const int l = l0 + t;
        const float af = biasF + f0 * sx[t][c] + f1 * sx[t + 1][c]
                               + f2 * sx[t + 2][c] + f3 * sx[t + 3][c];
        s_xch[((size_t)b * L_SZ + l) * D_INNER + d] = __float2half_rn(siluf(af));
        const float ab = biasB + r0 * sx[t + 6][c] + r1 * sx[t + 5][c]
                               + r2 * sx[t + 4][c] + r3 * sx[t + 3][c];
        s_xch[((size_t)NTOK + (size_t)b * L_SZ + (L_SZ - 1 - l)) * D_INNER + d] =
            __float2half_rn(siluf(ab));
    }
}

// ---------------- Selective scan v3: cp.async double-buffered, SCH=48 ----------------
#define ST   64
#define SCH  48
#define STHR 192

__global__ __launch_bounds__(STHR) void scan_kernel(
    const float* __restrict__ A_log_f, const float* __restrict__ D_f,
    const float* __restrict__ A_log_b, const float* __restrict__ D_b)
{
    const int dir = blockIdx.z;
    const int b   = blockIdx.y;
    const int d0  = blockIdx.x * SCH;
    const int tid = threadIdx.x;
    const int ch  = tid >> 2;
    const int sg  = tid & 3;
    const int d   = d0 + ch;

    const size_t dirTok = (size_t)dir * NTOK;
    const __half* xch = s_xch + dirTok * D_INNER;
    const float* dtp  = g_dt   + dirTok * D_INNER;
    const float* xdbl = g_xdbl + dirTok * XDBL_C;
    __half*      yout = s_yh   + dirTok * D_INNER;
    const float* Alog = dir ? A_log_b : A_log_f;
    const float* Dv   = dir ? D_b     : D_f;

    float A[4];
    #pragma unroll
    for (int j = 0; j < 4; j++) A[j] = -__expf(Alog[d * D_STATE + sg * 4 + j]);
    const float Dd = Dv[d];

    float h[4] = {0.f, 0.f, 0.f, 0.f};

    __shared__ __align__(16) __half su [2][ST][SCH];   // 12 KB
    __shared__ __align__(16) float  sdt[2][ST][SCH];   // 24 KB
    __shared__ __align__(16) __half sz [2][ST][SCH];   // 12 KB
    __shared__ __align__(16) float  sbc[2][ST][32];    // 16 KB

    const uint32_t uSu  = smem_u32(su);
    const uint32_t uSdt = smem_u32(sdt);
    const uint32_t uSz  = smem_u32(sz);
    const uint32_t uSbc = smem_u32(sbc);

    const int nch = L_SZ / ST;

    auto stage = [&](int c, int buf) {
        const int l0 = c * ST;
        // u: 6 cp16 per row (96 B), 384 total
        for (int i = tid; i < ST * 6; i += STHR) {
            const int t = i / 6, j = i % 6;
            const __half* src = xch + ((size_t)b * L_SZ + l0 + t) * D_INNER + d0 + j * 8;
            cp16(uSu + (uint32_t)(((buf * ST + t) * SCH) * 2 + j * 16), src, true);
        }
        // dt: 12 cp16 per row (192 B), 768 total
        for (int i = tid; i < ST * 12; i += STHR) {
            const int t = i / 12, j = i % 12;
            const float* src = dtp + ((size_t)b * L_SZ + l0 + t) * D_INNER + d0 + j * 4;
            cp16(uSdt + (uint32_t)(((buf * ST + t) * SCH) * 4 + j * 16), src, true);
        }
        // z: 6 cp16 per row, reversed rows for dir=1
        for (int i = tid; i < ST * 6; i += STHR) {
            const int t = i / 6, j = i % 6;
            const int lsrc = dir ? (L_SZ - 1 - (l0 + t)) : (l0 + t);
            const __half* src = s_zh + ((size_t)b * L_SZ + lsrc) * D_INNER + d0 + j * 8;
            cp16(uSz + (uint32_t)(((buf * ST + t) * SCH) * 2 + j * 16), src, true);
        }
        // B|C: 8 cp16 per row (128 B), 512 total
        for (int i = tid; i < ST * 8; i += STHR) {
            const int t = i / 8, j = i % 8;
            const float* src = xdbl + ((size_t)b * L_SZ + l0 + t) * XDBL_C + DT_RANK + j * 4;
            cp16(uSbc + (uint32_t)(((buf * ST + t) * 32) * 4 + j * 16), src, true);
        }
        asm volatile("cp.async.commit_group;" ::: "memory");
    };

    stage(0, 0);

    for (int c = 0; c < nch; c++) {
        const int buf = c & 1;
        if (c + 1 < nch) {
            stage(c + 1, (c + 1) & 1);
            asm volatile("cp.async.wait_group 1;" ::: "memory");
        } else {
            asm volatile("cp.async.wait_group 0;" ::: "memory");
        }
        __syncthreads();

        const int l0 = c * ST;
        for (int t = 0; t < ST; t++) {
            const float u   = __half2float(su[buf][t][ch]);
            const float dtv = sdt[buf][t][ch];
            const float dtu = dtv * u;
            const float4 Bv = *(const float4*)&sbc[buf][t][sg * 4];
            const float4 Cv = *(const float4*)&sbc[buf][t][16 + sg * 4];
            float y;
            {
                const float dA0 = __expf(dtv * A[0]);
                const float dA1 = __expf(dtv * A[1]);
                const float dA2 = __expf(dtv * A[2]);
                const float dA3 = __expf(dtv * A[3]);
                h[0] = h[0] * dA0 + dtu * Bv.x;
                h[1] = h[1] * dA1 + dtu * Bv.y;
                h[2] = h[2] * dA2 + dtu * Bv.z;
                h[3] = h[3] * dA3 + dtu * Bv.w;
                y = h[0] * Cv.x + h[1] * Cv.y + h[2] * Cv.z + h[3] * Cv.w;
            }
            y += __shfl_xor_sync(0xFFFFFFFF, y, 1);
            y += __shfl_xor_sync(0xFFFFFFFF, y, 2);
            if (sg == 0) {
                y += u * Dd;
                const int l = l0 + t;
                const int lsrc = dir ? (L_SZ - 1 - l) : l;
                const float zv = __half2float(sz[buf][t][ch]);
                yout[((size_t)b * L_SZ + lsrc) * D_INNER + d] =
                    __float2half_rn(y * siluf(zv));
            }
        }
        __syncthreads();  // all reads of buf done before stage(c+2) overwrites it
    }
}

// ---------------- Launch ----------------
extern "C" void kernel_launch(void* const* d_in, const int* in_sizes, int n_in,
                              void* d_out, int out_size)
{
    const float* x            = (const float*)d_in[0];
    const float* in_proj_w    = (const float*)d_in[1];
    const float* out_proj_w   = (const float*)d_in[2];
    const float* conv1d_w     = (const float*)d_in[3];
    const float* conv1d_bias  = (const float*)d_in[4];
    const float* x_proj_w     = (const float*)d_in[5];
    const float* dt_proj_w    = (const float*)d_in[6];
    const float* dt_proj_bias = (const float*)d_in[7];
    const float* A_log        = (const float*)d_in[8];
    const float* Dvec         = (const float*)d_in[9];
    const float* conv1d_w_b   = (const float*)d_in[10];
    const float* conv1d_bias_b= (const float*)d_in[11];
    const float* x_proj_w_b   = (const float*)d_in[12];
    const float* dt_proj_w_b  = (const float*)d_in[13];
    const float* dt_proj_bias_b=(const float*)d_in[14];
    const float* A_log_b      = (const float*)d_in[15];
    const float* D_b          = (const float*)d_in[16];
    float* out = (float*)d_out;

    float *p_dt, *p_xdbl;
    __half *p_xf,*p_zh,*p_yh,*p_ysum,*p_xh,*p_wi,*p_wo,*p_wx,*p_wd,*p_xch,*p_dtrh;
    cudaGetSymbolAddress((void**)&p_dt,   g_dt);
    cudaGetSymbolAddress((void**)&p_xdbl, g_xdbl);
    cudaGetSymbolAddress((void**)&p_xf,   s_xf);
    cudaGetSymbolAddress((void**)&p_zh,   s_zh);
    cudaGetSymbolAddress((void**)&p_yh,   s_yh);
    cudaGetSymbolAddress((void**)&p_ysum, s_ysum);
    cudaGetSymbolAddress((void**)&p_xh,   s_xh);
    cudaGetSymbolAddress((void**)&p_wi,   s_wi);
    cudaGetSymbolAddress((void**)&p_wo,   s_wo);
    cudaGetSymbolAddress((void**)&p_wx,   s_wx);
    cudaGetSymbolAddress((void**)&p_wd,   s_wd);
    cudaGetSymbolAddress((void**)&p_xch,  s_xch);
    cudaGetSymbolAddress((void**)&p_dtrh, s_dtrh);

    cudaFuncSetAttribute((const void*)gemm_sp<256>, cudaFuncAttributeMaxDynamicSharedMemorySize,
                         NSTAGE * (10240 + 256 * 80));
    cudaFuncSetAttribute((const void*)gemm_sp<128>, cudaFuncAttributeMaxDynamicSharedMemorySize,
                         NSTAGE * (10240 + 128 * 80));

    const size_t tokDI = (size_t)NTOK * D_INNER;
    const size_t tokXD = (size_t)NTOK * XDBL_C;
    const size_t wx1   = (size_t)XDBL_C * D_INNER;
    const size_t wd1   = (size_t)D_INNER * DT_RANK;
    const size_t dtr1  = (size_t)NTOK * DT_RANK;

    // 1) small weights
    {
        CvtSegs cs{};
        cs.src[0] = x_proj_w;    cs.dst[0] = p_wx;        cs.n4[0] = (int)(wx1 / 4);
        cs.src[1] = x_proj_w_b;  cs.dst[1] = p_wx + wx1;  cs.n4[1] = (int)(wx1 / 4);
        cs.src[2] = dt_proj_w;   cs.dst[2] = p_wd;        cs.n4[2] = (int)(wd1 / 4);
        cs.src[3] = dt_proj_w_b; cs.dst[3] = p_wd + wd1;  cs.n4[3] = (int)(wd1 / 4);
        cs.nseg = 4;
        cvt_all<<<512, 256>>>(cs, cs.n4[0] + cs.n4[1] + cs.n4[2] + cs.n4[3]);
    }
    // 2) big weights
    {
        CvtSegs cs{};
        cs.src[0] = in_proj_w;   cs.dst[0] = p_wi;  cs.n4[0] = E2 * DIM / 4;
        cs.src[1] = out_proj_w;  cs.dst[1] = p_wo;  cs.n4[1] = DIM * D_INNER / 4;
        cs.nseg = 2;
        cvt_all<<<2048, 256>>>(cs, cs.n4[0] + cs.n4[1]);
    }
    // 3) x
    {
        CvtSegs cs{};
        cs.src[0] = x; cs.dst[0] = p_xh; cs.n4[0] = NTOK * DIM / 4;
        cs.nseg = 1;
        cvt_all<<<2048, 256>>>(cs, cs.n4[0]);
    }

    // 4) in_proj (16384 x 3072, K=768), both halves -> fp16  <-- PROFILED
    {
        GArg a{p_xh, p_wi, nullptr, nullptr, p_zh, p_xf};
        dim3 grid(E2 / 256, NTOK / BM, 1);
        gemm_sp<256><<<grid, 512, NSTAGE*(10240+256*80)>>>(a, a, DIM, DIM, D_INNER, NTOK, E2, DIM, 3);
    }

    // 5) fused bidirectional conv + silu
    {
        dim3 grid(D_INNER / CCH, L_SZ / CTOK, B_SZ);
        conv_silu_kernel<<<grid, 256>>>(conv1d_w, conv1d_bias, conv1d_w_b, conv1d_bias_b);
    }

    // 6) x_proj both dirs (16384 x 80, K=1536)
    {
        GArg a0{p_xch,         p_wx,       nullptr, p_xdbl,         p_dtrh,        nullptr};
        GArg a1{p_xch + tokDI, p_wx + wx1, nullptr, p_xdbl + tokXD, p_dtrh + dtr1, nullptr};
        dim3 grid(1, NTOK / BM, 2);
        gemm_sp<128><<<grid, 512, NSTAGE*(10240+128*80)>>>(a0, a1, D_INNER, D_INNER, XDBL_C, NTOK, XDBL_C, D_INNER, 2);
    }

    // 7) dt_proj both dirs (16384 x 1536, K=48) + softplus
    {
        GArg a0{p_dtrh,        p_wd,       dt_proj_bias,   p_dt,         nullptr, nullptr};
        GArg a1{p_dtrh + dtr1, p_wd + wd1, dt_proj_bias_b, p_dt + tokDI, nullptr, nullptr};
        dim3 grid(D_INNER / 256, NTOK / BM, 2);
        gemm_sp<256><<<grid, 512, NSTAGE*(10240+256*80)>>>(a0, a1, DT_RANK, DT_RANK, D_INNER, NTOK, D_INNER, DT_RANK, 1);
    }

    // 8) selective scan v3 (cp.async double-buffered, SCH=48)
    {
        dim3 grid(D_INNER / SCH, B_SZ, 2);
        scan_kernel<<<grid, STHR>>>(A_log, Dvec, A_log_b, D_b);
    }

    // 9) ysum
    ysum_kernel<<<1024, 256>>>((int)(tokDI / 4));

    // 10) out_proj (16384 x 768, K=1536)
    {
        GArg a{p_ysum, p_wo, nullptr, out, nullptr, nullptr};
        dim3 grid(DIM / 256, NTOK / BM, 1);
        gemm_sp<256><<<grid, 512, NSTAGE*(10240+256*80)>>>(a, a, D_INNER, D_INNER, DIM, NTOK, DIM, D_INNER, 0);
    }
}